// round 6
// baseline (speedup 1.0000x reference)
#include <cuda_runtime.h>
#include <cuda_fp16.h>
#include <cstdint>

// ---------------------------------------------------------------------------
// SSIM loss, fused tiled kernel, R6: f32x2-packed FMA (issue-bound regime).
//   - phase A/B accumulate in packed fp32x2 pairs (fma.rn.f32x2, sm_100+)
//   - fp16 hbuf (26.6KB smem), 256-thr CTAs, 5 CTAs/SM
//   - last-block finalize in-kernel
// Shapes fixed: (16,3,512,512) fp32 inputs, scalar fp32 out.
// ---------------------------------------------------------------------------

#define IMG_W   512
#define IMG_H   512
#define NPLANES 48
#define NPIX    (48LL * 512 * 512)

#define TILE_X  32
#define TILE_Y  64
#define HALO 5
#define RH   (TILE_Y + 2 * HALO)         // 74 rows of horizontal output
#define HS   36                          // hbuf row stride in halfs
#define QS   (RH * HS)                   // halfs per quantity plane
#define HBUF_HALFS (5 * QS)              // 13320 -> 26640 B
#define NJOBS (RH * 8)                   // 592 jobs (8 segs of 4 outputs)
#define NBLOCKS (16 * 8 * 48)            // 6144

#define C1_ 0.0001f
#define C2_ 0.0009f

__device__ double g_sum;            // static-init 0
__device__ unsigned int g_count;    // static-init 0

typedef unsigned long long u64p;

// 1-D Gaussian, sigma=1.5, 11 taps; 0 outside [0,10].
__device__ __forceinline__ float wt(int t) {
    const float G[11] = {0.00102838f, 0.00759876f, 0.03600077f, 0.10936070f,
                         0.21300554f, 0.26601172f, 0.21300554f, 0.10936070f,
                         0.03600077f, 0.00759876f, 0.00102838f};
    return (t >= 0 && t < 11) ? G[t] : 0.f;
}

__device__ __forceinline__ u64p pack2(float lo, float hi) {
    u64p r;
    asm("mov.b64 %0, {%1, %2};" : "=l"(r) : "f"(lo), "f"(hi));
    return r;
}
__device__ __forceinline__ void unpack2(u64p v, float& lo, float& hi) {
    asm("mov.b64 {%0, %1}, %2;" : "=f"(lo), "=f"(hi) : "l"(v));
}
__device__ __forceinline__ void ffma2(u64p& acc, u64p a, u64p b) {
    asm("fma.rn.f32x2 %0, %1, %2, %0;" : "+l"(acc) : "l"(a), "l"(b));
}

// One horizontal tap k into packed accumulators (outputs j=0..3 as 2 pairs).
__device__ __forceinline__ void accum_tap2(float a, float b, int k, u64p acc2[5][2]) {
    float aa = a * a;
    float bb = b * b;
    float ab = a * b;
    u64p va  = pack2(a,  a);
    u64p vb  = pack2(b,  b);
    u64p vaa = pack2(aa, aa);
    u64p vbb = pack2(bb, bb);
    u64p vab = pack2(ab, ab);
    #pragma unroll
    for (int p = 0; p < 2; p++) {
        int t = k - 2 * p;                  // lane0 weight index (output 2p)
        if (t >= 0 && t <= 11) {            // at least one lane live
            u64p w2 = pack2(wt(t), wt(t - 1));
            ffma2(acc2[0][p], va,  w2);
            ffma2(acc2[1][p], vb,  w2);
            ffma2(acc2[2][p], vaa, w2);
            ffma2(acc2[3][p], vbb, w2);
            ffma2(acc2[4][p], vab, w2);
        }
    }
}

// Vertical conv pass: 18 fp16 SMEM taps -> 8 outputs as 4 packed pairs.
__device__ __forceinline__ void vpass2(const __half* __restrict__ col, float out[8]) {
    u64p acc[4] = {0ull, 0ull, 0ull, 0ull};
    #pragma unroll
    for (int k = 0; k < 18; k++) {
        float v = __half2float(col[k * HS]);
        u64p v2 = pack2(v, v);
        #pragma unroll
        for (int p = 0; p < 4; p++) {
            int t = k - 2 * p;
            if (t >= 0 && t <= 11) {
                u64p w2 = pack2(wt(t), wt(t - 1));
                ffma2(acc[p], v2, w2);
            }
        }
    }
    #pragma unroll
    for (int p = 0; p < 4; p++) unpack2(acc[p], out[2 * p], out[2 * p + 1]);
}

__global__ __launch_bounds__(256, 5)
void ssim_kernel(const float* __restrict__ img1, const float* __restrict__ img2,
                 float* __restrict__ out) {
    extern __shared__ __half hb[];       // 5 * QS halfs
    __shared__ float red[8];

    const int tid   = threadIdx.x;
    const int plane = blockIdx.z;
    const int x0    = blockIdx.x * TILE_X;
    const int y0    = blockIdx.y * TILE_Y;

    const float* p1 = img1 + (size_t)plane * (IMG_W * IMG_H);
    const float* p2 = img2 + (size_t)plane * (IMG_W * IMG_H);

    // ---- Phase A: horizontal conv of 5 quantities straight from gmem.
    //      Job = 4 consecutive x outputs of one row (14 taps). ----
    for (int job = tid; job < NJOBS; job += 256) {
        const int row = job >> 3;
        const int xs  = (job & 7) * 4;
        const int gy  = y0 - HALO + row;
        const bool yok = ((unsigned)gy < IMG_H);

        const int xbase = x0 - HALO + xs;     // first tap x (may be <0)
        const int a0    = xbase - 3;          // 16B-aligned vector base
        const bool vec_ok = yok && (a0 >= 0) && (a0 + 16 < IMG_W);

        u64p acc2[5][2];
        #pragma unroll
        for (int q = 0; q < 5; q++) { acc2[q][0] = 0ull; acc2[q][1] = 0ull; }

        if (vec_ok) {
            const float* b1 = p1 + (size_t)gy * IMG_W + a0;
            const float* b2 = p2 + (size_t)gy * IMG_W + a0;
            // batch 1: t[0..7] -> taps k=0..4 (uses t[3..7])
            {
                float4 A0 = __ldg((const float4*)(b1 + 0));
                float4 A1 = __ldg((const float4*)(b1 + 4));
                float4 B0 = __ldg((const float4*)(b2 + 0));
                float4 B1 = __ldg((const float4*)(b2 + 4));
                float ta[8] = {A0.x, A0.y, A0.z, A0.w, A1.x, A1.y, A1.z, A1.w};
                float tb[8] = {B0.x, B0.y, B0.z, B0.w, B1.x, B1.y, B1.z, B1.w};
                #pragma unroll
                for (int k = 0; k < 5; k++)
                    accum_tap2(ta[k + 3], tb[k + 3], k, acc2);
            }
            // batch 2: t[8..16] -> taps k=5..13
            {
                float4 A2 = __ldg((const float4*)(b1 + 8));
                float4 A3 = __ldg((const float4*)(b1 + 12));
                float4 B2 = __ldg((const float4*)(b2 + 8));
                float4 B3 = __ldg((const float4*)(b2 + 12));
                float a16 = __ldg(b1 + 16);
                float b16 = __ldg(b2 + 16);
                float ta[9] = {A2.x, A2.y, A2.z, A2.w, A3.x, A3.y, A3.z, A3.w, a16};
                float tb[9] = {B2.x, B2.y, B2.z, B2.w, B3.x, B3.y, B3.z, B3.w, b16};
                #pragma unroll
                for (int k = 5; k < 14; k++)
                    accum_tap2(ta[k - 5], tb[k - 5], k, acc2);
            }
        } else if (yok) {
            const float* r1 = p1 + (size_t)gy * IMG_W + xbase;
            const float* r2 = p2 + (size_t)gy * IMG_W + xbase;
            #pragma unroll
            for (int k = 0; k < 14; k++) {
                bool ok = ((unsigned)(xbase + k) < IMG_W);
                float a = ok ? __ldg(r1 + k) : 0.f;
                float b = ok ? __ldg(r2 + k) : 0.f;
                accum_tap2(a, b, k, acc2);
            }
        }
        // else: out-of-image row -> zeros (acc2 already 0)

        #pragma unroll
        for (int q = 0; q < 5; q++) {
            float x0f, x1f, x2f, x3f;
            unpack2(acc2[q][0], x0f, x1f);
            unpack2(acc2[q][1], x2f, x3f);
            __half2* dst = (__half2*)(hb + q * QS + row * HS + xs);
            dst[0] = __floats2half2_rn(x0f, x1f);
            dst[1] = __floats2half2_rn(x2f, x3f);
        }
    }
    __syncthreads();

    // ---- Phase B: vertical conv + SSIM epilogue. One x column, 8 y
    //      outputs per thread (packed pairs inside vpass2). ----
    float psum = 0.f;
    {
        const int x     = tid & 31;
        const int ybase = (tid >> 5) * 8;
        const __half* base = hb + ybase * HS + x;

        float mu1[8], mu2[8], e11[8], e22[8], e12[8];
        vpass2(base + 0 * QS, mu1);
        vpass2(base + 1 * QS, mu2);
        vpass2(base + 2 * QS, e11);
        vpass2(base + 3 * QS, e22);
        vpass2(base + 4 * QS, e12);

        #pragma unroll
        for (int j = 0; j < 8; j++) {
            float m1   = mu1[j], m2 = mu2[j];
            float m1m1 = m1 * m1;
            float m2m2 = m2 * m2;
            float m1m2 = m1 * m2;
            float sig1  = e11[j] - m1m1;
            float sig2  = e22[j] - m2m2;
            float sig12 = e12[j] - m1m2;
            float num = (2.f * m1m2 + C1_) * (2.f * sig12 + C2_);
            float den = (m1m1 + m2m2 + C1_) * (sig1 + sig2 + C2_);
            psum += __fdividef(num, den);
        }
    }

    // ---- Phase C: block reduction -> one double atomic; last block
    //      finalizes the scalar output and resets the accumulators. ----
    #pragma unroll
    for (int off = 16; off; off >>= 1)
        psum += __shfl_down_sync(0xffffffffu, psum, off);
    if ((tid & 31) == 0) red[tid >> 5] = psum;
    __syncthreads();
    if (tid == 0) {
        float v = 0.f;
        #pragma unroll
        for (int w = 0; w < 8; w++) v += red[w];
        atomicAdd(&g_sum, (double)v);
        __threadfence();
        unsigned int c = atomicAdd(&g_count, 1u);
        if (c == NBLOCKS - 1) {
            out[0] = (float)(1.0 - g_sum / (double)NPIX);
            g_sum   = 0.0;           // ready for next graph replay
            g_count = 0u;
        }
    }
}

extern "C" void kernel_launch(void* const* d_in, const int* in_sizes, int n_in,
                              void* d_out, int out_size) {
    const float* img1 = (const float*)d_in[0];
    const float* img2 = (const float*)d_in[1];
    float* out = (float*)d_out;

    const size_t smem_bytes = (size_t)HBUF_HALFS * sizeof(__half);   // 26640 B
    cudaFuncSetAttribute(ssim_kernel,
                         cudaFuncAttributeMaxDynamicSharedMemorySize,
                         (int)smem_bytes);

    dim3 grid(IMG_W / TILE_X, IMG_H / TILE_Y, NPLANES);
    ssim_kernel<<<grid, 256, smem_bytes>>>(img1, img2, out);
}

// round 9
// speedup vs baseline: 1.0367x; 1.0367x over previous
#include <cuda_runtime.h>
#include <cuda_fp16.h>
#include <cstdint>

// ---------------------------------------------------------------------------
// SSIM loss, fused tiled kernel, R9 (= R7 design, mul.f32x2-free).
//   - phase A: accAB=(convA,convB), accSQ=(convA2,convB2); squares built with
//     fma.rn.f32x2 into zero (avoids mul.rn.f32x2 opcode entirely)
//   - hbuf interleaved fp16: planeAB half2, planeSQ half2, planeXP half
//   - phase B: 3 passes (AB/SQ packed FFMA2, XP scalar)
//   - 256-thr CTAs, 5 CTAs/SM, last-block finalize
// Shapes fixed: (16,3,512,512) fp32 inputs, scalar fp32 out.
// ---------------------------------------------------------------------------

#define IMG_W   512
#define IMG_H   512
#define NPLANES 48
#define NPIX    (48LL * 512 * 512)

#define TILE_X  32
#define TILE_Y  64
#define HALO 5
#define RH   (TILE_Y + 2 * HALO)         // 74 rows of horizontal output
#define HS   36                          // x stride (elements) in hbuf planes
#define PS   (RH * HS)                   // elements per plane (2664)
#define HBUF_U32 (2 * PS + PS / 2)       // 6660 u32 = 26640 B
#define NJOBS (RH * 8)                   // 592 jobs (8 segs of 4 outputs)
#define NBLOCKS (16 * 8 * 48)            // 6144

#define C1_ 0.0001f
#define C2_ 0.0009f

__device__ double g_sum;            // static-init 0
__device__ unsigned int g_count;    // static-init 0

typedef unsigned long long u64p;

// 1-D Gaussian, sigma=1.5, 11 taps.
__device__ __forceinline__ float wt(int t) {
    const float G[11] = {0.00102838f, 0.00759876f, 0.03600077f, 0.10936070f,
                         0.21300554f, 0.26601172f, 0.21300554f, 0.10936070f,
                         0.03600077f, 0.00759876f, 0.00102838f};
    return (t >= 0 && t < 11) ? G[t] : 0.f;
}

__device__ __forceinline__ u64p pack2(float lo, float hi) {
    u64p r;
    asm("mov.b64 %0, {%1, %2};" : "=l"(r) : "f"(lo), "f"(hi));
    return r;
}
__device__ __forceinline__ void unpack2(u64p v, float& lo, float& hi) {
    asm("mov.b64 {%0, %1}, %2;" : "=f"(lo), "=f"(hi) : "l"(v));
}
__device__ __forceinline__ void ffma2(u64p& acc, u64p a, u64p b) {
    asm("fma.rn.f32x2 %0, %1, %2, %0;" : "+l"(acc) : "l"(a), "l"(b));
}
__device__ __forceinline__ u64p wpair(int t) {     // (w,w), compile-time w
    float w = wt(t);
    return pack2(w, w);
}
__device__ __forceinline__ uint32_t h2bits(float lo, float hi) {
    __half2 h = __floats2half2_rn(lo, hi);
    return *reinterpret_cast<uint32_t*>(&h);
}

// One horizontal tap k: a,b from the two images.
__device__ __forceinline__ void tapAB(float a, float b, int k,
                                      u64p accAB[4], u64p accSQ[4], float accXP[4]) {
    u64p vab = pack2(a, b);
    u64p vsq = 0ull;
    ffma2(vsq, vab, vab);            // (a*a, b*b), FFMA2 only
    float ab = a * b;
    #pragma unroll
    for (int j = 0; j < 4; j++) {
        int t = k - j;
        if (t >= 0 && t < 11) {
            u64p w2 = wpair(t);
            ffma2(accAB[j], vab, w2);
            ffma2(accSQ[j], vsq, w2);
            accXP[j] = fmaf(wt(t), ab, accXP[j]);
        }
    }
}

__global__ __launch_bounds__(256, 5)
void ssim_kernel(const float* __restrict__ img1, const float* __restrict__ img2,
                 float* __restrict__ out) {
    extern __shared__ uint32_t hb32[];   // [AB: PS][SQ: PS][XP: PS/2]
    __shared__ float red[8];

    const int tid   = threadIdx.x;
    const int plane = blockIdx.z;
    const int x0    = blockIdx.x * TILE_X;
    const int y0    = blockIdx.y * TILE_Y;

    const float* p1 = img1 + (size_t)plane * (IMG_W * IMG_H);
    const float* p2 = img2 + (size_t)plane * (IMG_W * IMG_H);

    // ---- Phase A: horizontal conv straight from gmem, paired lanes. ----
    for (int job = tid; job < NJOBS; job += 256) {
        const int row = job >> 3;
        const int xs  = (job & 7) * 4;
        const int gy  = y0 - HALO + row;
        const bool yok = ((unsigned)gy < IMG_H);

        const int xbase = x0 - HALO + xs;     // first tap x (may be <0)
        const int a0    = xbase - 3;          // 16B-aligned vector base
        const bool vec_ok = yok && (a0 >= 0) && (a0 + 16 < IMG_W);

        u64p accAB[4], accSQ[4];
        float accXP[4];
        #pragma unroll
        for (int j = 0; j < 4; j++) { accAB[j] = 0ull; accSQ[j] = 0ull; accXP[j] = 0.f; }

        if (vec_ok) {
            const float* b1 = p1 + (size_t)gy * IMG_W + a0;
            const float* b2 = p2 + (size_t)gy * IMG_W + a0;
            // batch 1: t[0..7] -> taps k=0..4 (uses t[3..7])
            {
                float4 A0 = __ldg((const float4*)(b1 + 0));
                float4 A1 = __ldg((const float4*)(b1 + 4));
                float4 B0 = __ldg((const float4*)(b2 + 0));
                float4 B1 = __ldg((const float4*)(b2 + 4));
                float ta[8] = {A0.x, A0.y, A0.z, A0.w, A1.x, A1.y, A1.z, A1.w};
                float tb[8] = {B0.x, B0.y, B0.z, B0.w, B1.x, B1.y, B1.z, B1.w};
                #pragma unroll
                for (int k = 0; k < 5; k++)
                    tapAB(ta[k + 3], tb[k + 3], k, accAB, accSQ, accXP);
            }
            // batch 2: t[8..16] -> taps k=5..13
            {
                float4 A2 = __ldg((const float4*)(b1 + 8));
                float4 A3 = __ldg((const float4*)(b1 + 12));
                float4 B2 = __ldg((const float4*)(b2 + 8));
                float4 B3 = __ldg((const float4*)(b2 + 12));
                float a16 = __ldg(b1 + 16);
                float b16 = __ldg(b2 + 16);
                float ta[9] = {A2.x, A2.y, A2.z, A2.w, A3.x, A3.y, A3.z, A3.w, a16};
                float tb[9] = {B2.x, B2.y, B2.z, B2.w, B3.x, B3.y, B3.z, B3.w, b16};
                #pragma unroll
                for (int k = 5; k < 14; k++)
                    tapAB(ta[k - 5], tb[k - 5], k, accAB, accSQ, accXP);
            }
        } else if (yok) {
            const float* r1 = p1 + (size_t)gy * IMG_W + xbase;
            const float* r2 = p2 + (size_t)gy * IMG_W + xbase;
            #pragma unroll
            for (int k = 0; k < 14; k++) {
                bool ok = ((unsigned)(xbase + k) < IMG_W);
                float a = ok ? __ldg(r1 + k) : 0.f;
                float b = ok ? __ldg(r2 + k) : 0.f;
                tapAB(a, b, k, accAB, accSQ, accXP);
            }
        }
        // else: out-of-image row -> zeros

        // Interleaved fp16 stores: AB and SQ as half2 planes, XP as half.
        {
            const int eidx = row * HS + xs;      // multiple of 4
            uint4 uab, usq;
            float fa, fb;
            unpack2(accAB[0], fa, fb); uab.x = h2bits(fa, fb);
            unpack2(accAB[1], fa, fb); uab.y = h2bits(fa, fb);
            unpack2(accAB[2], fa, fb); uab.z = h2bits(fa, fb);
            unpack2(accAB[3], fa, fb); uab.w = h2bits(fa, fb);
            unpack2(accSQ[0], fa, fb); usq.x = h2bits(fa, fb);
            unpack2(accSQ[1], fa, fb); usq.y = h2bits(fa, fb);
            unpack2(accSQ[2], fa, fb); usq.z = h2bits(fa, fb);
            unpack2(accSQ[3], fa, fb); usq.w = h2bits(fa, fb);
            *(uint4*)(hb32 + eidx)      = uab;
            *(uint4*)(hb32 + PS + eidx) = usq;
            uint2 uxp = make_uint2(h2bits(accXP[0], accXP[1]),
                                   h2bits(accXP[2], accXP[3]));
            *(uint2*)(hb32 + 2 * PS + (eidx >> 1)) = uxp;
        }
    }
    __syncthreads();

    // ---- Phase B: vertical conv, 3 passes, + SSIM epilogue. ----
    float psum = 0.f;
    {
        const int x     = tid & 31;
        const int ybase = (tid >> 5) * 8;

        float mu1[8], mu2[8], e11[8], e22[8], e12[8];

        // pass AB -> (mu1, mu2)
        {
            u64p acc[8];
            #pragma unroll
            for (int j = 0; j < 8; j++) acc[j] = 0ull;
            const uint32_t* p = hb32 + ybase * HS + x;
            #pragma unroll
            for (int k = 0; k < 18; k++) {
                uint32_t ub = p[k * HS];
                __half2 h = *reinterpret_cast<const __half2*>(&ub);
                float2 f = __half22float2(h);
                u64p v2 = pack2(f.x, f.y);
                #pragma unroll
                for (int j = 0; j < 8; j++) {
                    int t = k - j;
                    if (t >= 0 && t < 11) ffma2(acc[j], v2, wpair(t));
                }
            }
            #pragma unroll
            for (int j = 0; j < 8; j++) unpack2(acc[j], mu1[j], mu2[j]);
        }
        // pass SQ -> (e11, e22)
        {
            u64p acc[8];
            #pragma unroll
            for (int j = 0; j < 8; j++) acc[j] = 0ull;
            const uint32_t* p = hb32 + PS + ybase * HS + x;
            #pragma unroll
            for (int k = 0; k < 18; k++) {
                uint32_t ub = p[k * HS];
                __half2 h = *reinterpret_cast<const __half2*>(&ub);
                float2 f = __half22float2(h);
                u64p v2 = pack2(f.x, f.y);
                #pragma unroll
                for (int j = 0; j < 8; j++) {
                    int t = k - j;
                    if (t >= 0 && t < 11) ffma2(acc[j], v2, wpair(t));
                }
            }
            #pragma unroll
            for (int j = 0; j < 8; j++) unpack2(acc[j], e11[j], e22[j]);
        }
        // pass XP -> e12 (scalar)
        {
            float acc[8];
            #pragma unroll
            for (int j = 0; j < 8; j++) acc[j] = 0.f;
            const __half* p = (const __half*)(hb32 + 2 * PS) + ybase * HS + x;
            #pragma unroll
            for (int k = 0; k < 18; k++) {
                float v = __half2float(p[k * HS]);
                #pragma unroll
                for (int j = 0; j < 8; j++) {
                    int t = k - j;
                    if (t >= 0 && t < 11) acc[j] = fmaf(wt(t), v, acc[j]);
                }
            }
            #pragma unroll
            for (int j = 0; j < 8; j++) e12[j] = acc[j];
        }

        #pragma unroll
        for (int j = 0; j < 8; j++) {
            float m1   = mu1[j], m2 = mu2[j];
            float m1m1 = m1 * m1;
            float m2m2 = m2 * m2;
            float m1m2 = m1 * m2;
            float sig1  = e11[j] - m1m1;
            float sig2  = e22[j] - m2m2;
            float sig12 = e12[j] - m1m2;
            float num = (2.f * m1m2 + C1_) * (2.f * sig12 + C2_);
            float den = (m1m1 + m2m2 + C1_) * (sig1 + sig2 + C2_);
            psum += __fdividef(num, den);
        }
    }

    // ---- Phase C: block reduction -> one double atomic; last block
    //      finalizes the scalar output and resets the accumulators. ----
    #pragma unroll
    for (int off = 16; off; off >>= 1)
        psum += __shfl_down_sync(0xffffffffu, psum, off);
    if ((tid & 31) == 0) red[tid >> 5] = psum;
    __syncthreads();
    if (tid == 0) {
        float v = 0.f;
        #pragma unroll
        for (int w = 0; w < 8; w++) v += red[w];
        atomicAdd(&g_sum, (double)v);
        __threadfence();
        unsigned int c = atomicAdd(&g_count, 1u);
        if (c == NBLOCKS - 1) {
            out[0] = (float)(1.0 - g_sum / (double)NPIX);
            g_sum   = 0.0;           // ready for next graph replay
            g_count = 0u;
        }
    }
}

extern "C" void kernel_launch(void* const* d_in, const int* in_sizes, int n_in,
                              void* d_out, int out_size) {
    const float* img1 = (const float*)d_in[0];
    const float* img2 = (const float*)d_in[1];
    float* out = (float*)d_out;

    const size_t smem_bytes = (size_t)HBUF_U32 * sizeof(uint32_t);   // 26640 B
    cudaFuncSetAttribute(ssim_kernel,
                         cudaFuncAttributeMaxDynamicSharedMemorySize,
                         (int)smem_bytes);

    dim3 grid(IMG_W / TILE_X, IMG_H / TILE_Y, NPLANES);
    ssim_kernel<<<grid, 256, smem_bytes>>>(img1, img2, out);
}

// round 11
// speedup vs baseline: 1.2245x; 1.1812x over previous
#include <cuda_runtime.h>
#include <cuda_fp16.h>
#include <cstdint>

// ---------------------------------------------------------------------------
// SSIM loss, fused tiled kernel, R11 (= R10 resubmit after infra failure).
// Scalar FFMA (R5 structure), 4 convolved quantities instead of 5:
//   a, b, sq=a^2+b^2, xp=a*b        (e11,e22 never needed separately:
//   sig1+sig2 = conv(sq) - mu1^2 - mu2^2)
//   - fp16 hbuf (21.3KB smem), 256-thr CTAs, 5 CTAs/SM
//   - last-block finalize in-kernel
// Shapes fixed: (16,3,512,512) fp32 inputs, scalar fp32 out.
// ---------------------------------------------------------------------------

#define IMG_W   512
#define IMG_H   512
#define NPLANES 48
#define NPIX    (48LL * 512 * 512)

#define TILE_X  32
#define TILE_Y  64
#define HALO 5
#define RH   (TILE_Y + 2 * HALO)         // 74 rows of horizontal output
#define HS   36                          // hbuf row stride in halfs
#define QS   (RH * HS)                   // halfs per quantity plane (2664)
#define HBUF_HALFS (4 * QS)              // 10656 -> 21312 B
#define NJOBS (RH * 8)                   // 592 jobs (8 segs of 4 outputs)
#define NBLOCKS (16 * 8 * 48)            // 6144

#define GW {0.00102838f, 0.00759876f, 0.03600077f, 0.10936070f, 0.21300554f, \
            0.26601172f, 0.21300554f, 0.10936070f, 0.03600077f, 0.00759876f, \
            0.00102838f}

#define C1_ 0.0001f
#define C2_ 0.0009f

__device__ double g_sum;            // static-init 0
__device__ unsigned int g_count;    // static-init 0

// Vertical conv pass: 18 strided fp16 SMEM loads -> 8 fp32 outputs.
__device__ __forceinline__ void vpass(const __half* __restrict__ col, float out[8]) {
    const float G[11] = GW;
    #pragma unroll
    for (int j = 0; j < 8; j++) out[j] = 0.f;
    #pragma unroll
    for (int k = 0; k < 18; k++) {
        float v = __half2float(col[k * HS]);
        #pragma unroll
        for (int j = 0; j < 8; j++) {
            int t = k - j;
            if (t >= 0 && t < 11) out[j] = fmaf(G[t], v, out[j]);
        }
    }
}

// One horizontal tap k into 4-quantity accumulators (4 outputs).
__device__ __forceinline__ void accum_tap(float a, float b, int k, float acc[4][4]) {
    const float G[11] = GW;
    float aa = a * a;
    float sq = fmaf(b, b, aa);       // a^2 + b^2
    float ab = a * b;
    #pragma unroll
    for (int j = 0; j < 4; j++) {
        int t = k - j;
        if (t >= 0 && t < 11) {
            float w = G[t];
            acc[0][j] = fmaf(w, a,  acc[0][j]);
            acc[1][j] = fmaf(w, b,  acc[1][j]);
            acc[2][j] = fmaf(w, sq, acc[2][j]);
            acc[3][j] = fmaf(w, ab, acc[3][j]);
        }
    }
}

__global__ __launch_bounds__(256, 5)
void ssim_kernel(const float* __restrict__ img1, const float* __restrict__ img2,
                 float* __restrict__ out) {
    extern __shared__ __half hb[];       // 4 * QS halfs
    __shared__ float red[8];

    const int tid   = threadIdx.x;
    const int plane = blockIdx.z;
    const int x0    = blockIdx.x * TILE_X;
    const int y0    = blockIdx.y * TILE_Y;

    const float* p1 = img1 + (size_t)plane * (IMG_W * IMG_H);
    const float* p2 = img2 + (size_t)plane * (IMG_W * IMG_H);

    // ---- Phase A: horizontal conv of 4 quantities straight from gmem.
    //      Job = 4 consecutive x outputs of one row (14 taps). ----
    for (int job = tid; job < NJOBS; job += 256) {
        const int row = job >> 3;
        const int xs  = (job & 7) * 4;
        const int gy  = y0 - HALO + row;
        const bool yok = ((unsigned)gy < IMG_H);

        const int xbase = x0 - HALO + xs;     // first tap x (may be <0)
        const int a0    = xbase - 3;          // 16B-aligned vector base
        const bool vec_ok = yok && (a0 >= 0) && (a0 + 16 < IMG_W);

        float acc[4][4];
        #pragma unroll
        for (int q = 0; q < 4; q++)
            #pragma unroll
            for (int j = 0; j < 4; j++) acc[q][j] = 0.f;

        if (vec_ok) {
            const float* b1 = p1 + (size_t)gy * IMG_W + a0;
            const float* b2 = p2 + (size_t)gy * IMG_W + a0;
            // batch 1: t[0..7] -> taps k=0..4 (uses t[3..7])
            {
                float4 A0 = __ldg((const float4*)(b1 + 0));
                float4 A1 = __ldg((const float4*)(b1 + 4));
                float4 B0 = __ldg((const float4*)(b2 + 0));
                float4 B1 = __ldg((const float4*)(b2 + 4));
                float ta[8] = {A0.x, A0.y, A0.z, A0.w, A1.x, A1.y, A1.z, A1.w};
                float tb[8] = {B0.x, B0.y, B0.z, B0.w, B1.x, B1.y, B1.z, B1.w};
                #pragma unroll
                for (int k = 0; k < 5; k++)
                    accum_tap(ta[k + 3], tb[k + 3], k, acc);
            }
            // batch 2: t[8..16] -> taps k=5..13
            {
                float4 A2 = __ldg((const float4*)(b1 + 8));
                float4 A3 = __ldg((const float4*)(b1 + 12));
                float4 B2 = __ldg((const float4*)(b2 + 8));
                float4 B3 = __ldg((const float4*)(b2 + 12));
                float a16 = __ldg(b1 + 16);
                float b16 = __ldg(b2 + 16);
                float ta[9] = {A2.x, A2.y, A2.z, A2.w, A3.x, A3.y, A3.z, A3.w, a16};
                float tb[9] = {B2.x, B2.y, B2.z, B2.w, B3.x, B3.y, B3.z, B3.w, b16};
                #pragma unroll
                for (int k = 5; k < 14; k++)
                    accum_tap(ta[k - 5], tb[k - 5], k, acc);
            }
        } else if (yok) {
            const float* r1 = p1 + (size_t)gy * IMG_W + xbase;
            const float* r2 = p2 + (size_t)gy * IMG_W + xbase;
            #pragma unroll
            for (int k = 0; k < 14; k++) {
                bool ok = ((unsigned)(xbase + k) < IMG_W);
                float a = ok ? __ldg(r1 + k) : 0.f;
                float b = ok ? __ldg(r2 + k) : 0.f;
                accum_tap(a, b, k, acc);
            }
        }
        // else: out-of-image row -> zeros (acc already 0)

        #pragma unroll
        for (int q = 0; q < 4; q++) {
            __half2* dst = (__half2*)(hb + q * QS + row * HS + xs);
            dst[0] = __floats2half2_rn(acc[q][0], acc[q][1]);
            dst[1] = __floats2half2_rn(acc[q][2], acc[q][3]);
        }
    }
    __syncthreads();

    // ---- Phase B: vertical conv (4 passes) + SSIM epilogue. ----
    float psum = 0.f;
    {
        const int x     = tid & 31;
        const int ybase = (tid >> 5) * 8;
        const __half* base = hb + ybase * HS + x;

        float mu1[8], mu2[8], esq[8], e12[8];
        vpass(base + 0 * QS, mu1);
        vpass(base + 1 * QS, mu2);
        vpass(base + 2 * QS, esq);
        vpass(base + 3 * QS, e12);

        #pragma unroll
        for (int j = 0; j < 8; j++) {
            float m1   = mu1[j], m2 = mu2[j];
            float m1m1 = m1 * m1;
            float m2m2 = m2 * m2;
            float m1m2 = m1 * m2;
            float msq  = m1m1 + m2m2;
            float sigs  = esq[j] - msq;          // sig1 + sig2
            float sig12 = e12[j] - m1m2;
            float num = (2.f * m1m2 + C1_) * (2.f * sig12 + C2_);
            float den = (msq + C1_) * (sigs + C2_);
            psum += __fdividef(num, den);
        }
    }

    // ---- Phase C: block reduction -> one double atomic; last block
    //      finalizes the scalar output and resets the accumulators. ----
    #pragma unroll
    for (int off = 16; off; off >>= 1)
        psum += __shfl_down_sync(0xffffffffu, psum, off);
    if ((tid & 31) == 0) red[tid >> 5] = psum;
    __syncthreads();
    if (tid == 0) {
        float v = 0.f;
        #pragma unroll
        for (int w = 0; w < 8; w++) v += red[w];
        atomicAdd(&g_sum, (double)v);
        __threadfence();
        unsigned int c = atomicAdd(&g_count, 1u);
        if (c == NBLOCKS - 1) {
            out[0] = (float)(1.0 - g_sum / (double)NPIX);
            g_sum   = 0.0;           // ready for next graph replay
            g_count = 0u;
        }
    }
}

extern "C" void kernel_launch(void* const* d_in, const int* in_sizes, int n_in,
                              void* d_out, int out_size) {
    const float* img1 = (const float*)d_in[0];
    const float* img2 = (const float*)d_in[1];
    float* out = (float*)d_out;

    const size_t smem_bytes = (size_t)HBUF_HALFS * sizeof(__half);   // 21312 B
    cudaFuncSetAttribute(ssim_kernel,
                         cudaFuncAttributeMaxDynamicSharedMemorySize,
                         (int)smem_bytes);

    dim3 grid(IMG_W / TILE_X, IMG_H / TILE_Y, NPLANES);
    ssim_kernel<<<grid, 256, smem_bytes>>>(img1, img2, out);
}